// round 10
// baseline (speedup 1.0000x reference)
#include <cuda_runtime.h>
#include <cuda_bf16.h>
#include <cstdint>

#define NV_V    100001
#define NV_VPAD 100096
#define NB      1024
#define NL      200
#define ND      64
#define NCH     782           // chunks of 128 vocab rows; coverage = 100096 = NV_VPAD
#define PAD_N   95.0f         // 100096 - 100001 zero rows, each contributes 2^0 = 1
#define GX      74
#define ESTRIDE 80            // smem row stride for 64B fp8 rows (conflict-free)
#define CVT_N   (NV_V * ND / 16)         // 400004 16-byte packs
#define CVT_B   ((CVT_N + 255) / 256)    // 1563 blocks

// ---------------- device-global scratch ----------------
__device__ __align__(256) uint8_t g_E8[(size_t)NV_VPAD * ND];   // e4m3 item_emb; tail rows zero
__device__ __align__(256) uint8_t g_Q8[NB * ND];                // e4m3 Q, pre-scaled by log2(e)
__device__ float g_Spart[NB][GX];                // partial denominators, row-contiguous
__device__ float g_LP[NB];                       // exact logit at pred[b]

__device__ __forceinline__ uint32_t smem_u32(const void* p) {
    uint32_t a;
    asm("{ .reg .u64 t; cvta.to.shared.u64 t, %1; cvt.u32.u64 %0, t; }" : "=r"(a) : "l"(p));
    return a;
}
__device__ __forceinline__ float ex2f(float x) {
    float r; asm("ex2.approx.ftz.f32 %0, %1;" : "=f"(r) : "f"(x)); return r;
}
__device__ __forceinline__ void cp_async16(uint32_t dst, const void* src) {
    asm volatile("cp.async.cg.shared.global [%0], [%1], 16;" :: "r"(dst), "l"(src) : "memory");
}
// pack (lo, hi) floats into e4m3x2 (low byte = lo)
__device__ __forceinline__ uint16_t cvt2_e4m3(float lo, float hi) {
    uint16_t r;
    asm("cvt.rn.satfinite.e4m3x2.f32 %0, %1, %2;" : "=h"(r) : "f"(hi), "f"(lo));
    return r;
}
__device__ __forceinline__ uint32_t cvt4_e4m3(float a, float b, float c, float d) {
    return (uint32_t)cvt2_e4m3(a, b) | ((uint32_t)cvt2_e4m3(c, d) << 16);
}

// ---------------- K1: fused [q-pooling | fp32 -> e4m3 convert] ----------------
__global__ __launch_bounds__(256) void prep_kernel(const int* __restrict__ log_seqs,
                                                   const int* __restrict__ pred,
                                                   const float* __restrict__ item_emb,
                                                   const float* __restrict__ attn_key,
                                                   const float* __restrict__ pos_emb) {
    __shared__ __nv_bfloat16 sseq[NL][ND + 2];    // 26.4 KB; 132B row stride
    __shared__ __align__(16) float4 stage[50][16]; // 12.8 KB fp32 gather staging
    __shared__ int   sids[NL];
    __shared__ float ssim[NL];
    __shared__ float skey[ND];
    __shared__ float sred[8];
    __shared__ float sq[4][ND];
    __shared__ float sqf[ND];

    const int t = threadIdx.x;

    if (blockIdx.x >= NB) {
        // ---- convert branch: 16 floats -> 16 e4m3 bytes per thread ----
        int i = (blockIdx.x - NB) * 256 + t;
        if (i < CVT_N) {
            const float4* src = reinterpret_cast<const float4*>(item_emb) + 4 * (size_t)i;
            float4 v0 = src[0], v1 = src[1], v2 = src[2], v3 = src[3];
            uint4 p;
            p.x = cvt4_e4m3(v0.x, v0.y, v0.z, v0.w);
            p.y = cvt4_e4m3(v1.x, v1.y, v1.z, v1.w);
            p.z = cvt4_e4m3(v2.x, v2.y, v2.z, v2.w);
            p.w = cvt4_e4m3(v3.x, v3.y, v3.z, v3.w);
            reinterpret_cast<uint4*>(g_E8)[i] = p;
        }
        return;
    }

    // ---- q-pooling branch ----
    const int b = blockIdx.x;
    const int w = t >> 5, lane = t & 31;
    if (t < ND) skey[t] = attn_key[t];
    if (t < NL) sids[t] = log_seqs[b * NL + t];
    __syncthreads();

    // gather: 4 quarters of 50 rows each, cp.async staging (800 segments in flight)
    const uint32_t stage_base = smem_u32(stage);
    for (int qt = 0; qt < 4; qt++) {
        for (int idx = t; idx < 800; idx += 256) {
            int r = idx >> 4, seg = idx & 15;
            int id = sids[qt * 50 + r];   // id==0 fetches the all-zero padding row
            cp_async16(stage_base + idx * 16, item_emb + (size_t)id * ND + seg * 4);
        }
        asm volatile("cp.async.commit_group;" ::: "memory");
        asm volatile("cp.async.wait_group 0;" ::: "memory");
        __syncthreads();
        for (int idx = t; idx < 800; idx += 256) {
            int r = idx >> 4, seg = idx & 15;
            int l = qt * 50 + r;
            int id = sids[l];
            float4 e = stage[r][seg];
            float4 p = *reinterpret_cast<const float4*>(pos_emb + l * ND + seg * 4);
            float v0 = 0.f, v1 = 0.f, v2 = 0.f, v3 = 0.f;
            if (id != 0) {
                v0 = fmaf(e.x, 8.f, p.x); v1 = fmaf(e.y, 8.f, p.y);
                v2 = fmaf(e.z, 8.f, p.z); v3 = fmaf(e.w, 8.f, p.w);
            }
            __nv_bfloat162* dst = reinterpret_cast<__nv_bfloat162*>(&sseq[l][seg * 4]);
            dst[0] = __floats2bfloat162_rn(v0, v1);
            dst[1] = __floats2bfloat162_rn(v2, v3);
        }
        __syncthreads();
    }

    // sim: thread-per-row dot product from smem (33-word row stride, conflict-free)
    if (t < NL) {
        const __nv_bfloat162* row = reinterpret_cast<const __nv_bfloat162*>(sseq[t]);
        float sim = 0.f;
        #pragma unroll
        for (int d2 = 0; d2 < 32; d2++) {
            __nv_bfloat162 sv = row[d2];
            sim = fmaf(__bfloat162float(__low2bfloat16(sv)),  skey[2 * d2],     sim);
            sim = fmaf(__bfloat162float(__high2bfloat16(sv)), skey[2 * d2 + 1], sim);
        }
        ssim[t] = (sids[t] != 0) ? sim : -1e30f;
    }
    __syncthreads();

    // softmax over L
    float v = (t < NL) ? ssim[t] : -1e30f;
    float m = v;
    #pragma unroll
    for (int o = 16; o > 0; o >>= 1) m = fmaxf(m, __shfl_xor_sync(0xFFFFFFFFu, m, o));
    if (lane == 0) sred[w] = m;
    __syncthreads();
    if (t == 0) { float mm = sred[0]; for (int i = 1; i < 8; i++) mm = fmaxf(mm, sred[i]); sred[0] = mm; }
    __syncthreads();
    const float mx = sred[0];
    __syncthreads();
    float e = (t < NL) ? __expf(v - mx) : 0.f;
    if (t < NL) ssim[t] = e;
    float s = e;
    #pragma unroll
    for (int o = 16; o > 0; o >>= 1) s += __shfl_xor_sync(0xFFFFFFFFu, s, o);
    if (lane == 0) sred[w] = s;
    __syncthreads();
    if (t == 0) { float ss = 0.f; for (int i = 0; i < 8; i++) ss += sred[i]; sred[0] = ss; }
    __syncthreads();
    const float inv = 1.0f / sred[0];

    // pass 2: Q[d] = sum_l attn_l * seqs[l][d]
    const int d = t & 63, gq = t >> 6;
    float acc = 0.f;
    for (int l = gq; l < NL; l += 4)
        acc += ssim[l] * __bfloat162float(sseq[l][d]);
    sq[gq][d] = acc;
    __syncthreads();
    if (t < ND) {
        float q = (sq[0][t] + sq[1][t] + sq[2][t] + sq[3][t]) * inv;
        sqf[t] = q * 1.44269504088896340736f;   // *log2(e), for fp8 Q
        int pid = pred[b];
        sq[0][t] = q * item_emb[(size_t)pid * ND + t];
    }
    __syncthreads();
    if (t < 32)   // pack Q to e4m3
        reinterpret_cast<uint16_t*>(g_Q8 + b * ND)[t] = cvt2_e4m3(sqf[2 * t], sqf[2 * t + 1]);
    if (t == 0) {
        float lp = 0.f;
        for (int i = 0; i < ND; i++) lp += sq[0][i];
        g_LP[b] = lp;
    }
}

// ---------------- K2: fused FP8 GEMM (mma.sync e4m3) + exp2-sum epilogue ----------------
// Grid (GX, 8). 128-row chunks, 3-stage cp.async ring; warp w owns 16 M rows.
__global__ __launch_bounds__(256) void gemm_kernel() {
    __shared__ __align__(16) char sE[3][128 * ESTRIDE];   // 30 KB ring
    const int t = threadIdx.x, w = t >> 5, lane = t & 31;
    const int g = lane >> 2, tg = lane & 3;
    const int m0 = blockIdx.y * 128 + w * 16;
    uint32_t sb[3] = { smem_u32(sE[0]), smem_u32(sE[1]), smem_u32(sE[2]) };

    // A fragments: Q8[m0..m0+16) x k[0..64), 2 k-groups of 32
    uint32_t a[2][4];
    #pragma unroll
    for (int kk = 0; kk < 2; kk++) {
        const uint8_t* q0 = g_Q8 + (m0 + g) * ND + kk * 32 + tg * 4;
        const uint8_t* q1 = g_Q8 + (m0 + g + 8) * ND + kk * 32 + tg * 4;
        a[kk][0] = *reinterpret_cast<const uint32_t*>(q0);
        a[kk][1] = *reinterpret_cast<const uint32_t*>(q1);
        a[kk][2] = *reinterpret_cast<const uint32_t*>(q0 + 16);
        a[kk][3] = *reinterpret_cast<const uint32_t*>(q1 + 16);
    }

    float sum0 = 0.f, sum1 = 0.f;
    const uint32_t soff = (t >> 2) * ESTRIDE + (t & 3) * 16;   // rows t/4 and t/4+64
    const uint32_t goff = t * 16;

    // prefetch stages 0 and 1 (8 KB each: 512 segments, 2 per thread)
    #pragma unroll
    for (int p = 0; p < 2; p++) {
        int cc = blockIdx.x + p * GX;
        if (cc < NCH) {
            const uint8_t* src = g_E8 + (size_t)cc * 8192;
            cp_async16(sb[p] + soff, src + goff);
            cp_async16(sb[p] + soff + 64 * ESTRIDE, src + goff + 4096);
        }
        asm volatile("cp.async.commit_group;" ::: "memory");
    }

    int ph = 0;
    for (int c = blockIdx.x; c < NCH; c += GX) {
        asm volatile("cp.async.wait_group 1;" ::: "memory");
        __syncthreads();

        int cn = c + 2 * GX;
        int pn = ph + 2; if (pn >= 3) pn -= 3;
        if (cn < NCH) {
            const uint8_t* src = g_E8 + (size_t)cn * 8192;
            cp_async16(sb[pn] + soff, src + goff);
            cp_async16(sb[pn] + soff + 64 * ESTRIDE, src + goff + 4096);
        }
        asm volatile("cp.async.commit_group;" ::: "memory");

        const char* buf = sE[ph];
        #pragma unroll
        for (int nt = 0; nt < 16; nt++) {
            float c0 = 0.f, c1 = 0.f, c2 = 0.f, c3 = 0.f;
            const char* bp = buf + (nt * 8 + g) * ESTRIDE + tg * 4;
            #pragma unroll
            for (int kk = 0; kk < 2; kk++) {
                uint32_t b0 = *reinterpret_cast<const uint32_t*>(bp + kk * 32);
                uint32_t b1 = *reinterpret_cast<const uint32_t*>(bp + kk * 32 + 16);
                asm volatile(
                    "mma.sync.aligned.m16n8k32.row.col.f32.e4m3.e4m3.f32 "
                    "{%0,%1,%2,%3}, {%4,%5,%6,%7}, {%8,%9}, {%0,%1,%2,%3};"
                    : "+f"(c0), "+f"(c1), "+f"(c2), "+f"(c3)
                    : "r"(a[kk][0]), "r"(a[kk][1]), "r"(a[kk][2]), "r"(a[kk][3]),
                      "r"(b0), "r"(b1));
            }
            sum0 += ex2f(c0) + ex2f(c1);   // rows m0+g
            sum1 += ex2f(c2) + ex2f(c3);   // rows m0+g+8
        }
        ph = ph + 1 == 3 ? 0 : ph + 1;
    }

    sum0 += __shfl_xor_sync(0xFFFFFFFFu, sum0, 1);
    sum0 += __shfl_xor_sync(0xFFFFFFFFu, sum0, 2);
    sum1 += __shfl_xor_sync(0xFFFFFFFFu, sum1, 1);
    sum1 += __shfl_xor_sync(0xFFFFFFFFu, sum1, 2);
    if (tg == 0) {
        g_Spart[m0 + g][blockIdx.x] = sum0;
        g_Spart[m0 + g + 8][blockIdx.x] = sum1;
    }
}

// ---------------- K3: reduce partials + final gather (warp per row) ----------------
__global__ __launch_bounds__(256) void final_kernel(float* __restrict__ out) {
    const int gw = (blockIdx.x * 256 + threadIdx.x) >> 5;
    const int lane = threadIdx.x & 31;
    if (gw < NB) {
        float s = 0.f;
        for (int x = lane; x < GX; x += 32) s += g_Spart[gw][x];
        #pragma unroll
        for (int o = 16; o > 0; o >>= 1) s += __shfl_xor_sync(0xFFFFFFFFu, s, o);
        if (lane == 0) out[gw] = __expf(g_LP[gw]) / (s - PAD_N);
    }
}

// ---------------- launch ----------------
extern "C" void kernel_launch(void* const* d_in, const int* in_sizes, int n_in,
                              void* d_out, int out_size) {
    const int*   log_seqs = (const int*)d_in[0];
    const int*   pred     = (const int*)d_in[1];
    const float* item_emb = (const float*)d_in[2];
    const float* attn_key = (const float*)d_in[3];
    const float* pos_emb  = (const float*)d_in[4];
    float* out = (float*)d_out;

    prep_kernel<<<NB + CVT_B, 256>>>(log_seqs, pred, item_emb, attn_key, pos_emb);
    gemm_kernel<<<dim3(GX, NB / 128, 1), 256>>>();
    final_kernel<<<NB * 32 / 256, 256>>>(out);
}

// round 11
// speedup vs baseline: 1.0591x; 1.0591x over previous
#include <cuda_runtime.h>
#include <cuda_bf16.h>
#include <cuda_fp16.h>
#include <cstdint>

#define NV_V    100001
#define NV_VPAD 100096
#define NB      1024
#define NL      200
#define ND      64
#define NCH     782           // chunks of 128 vocab rows; coverage = 100096 = NV_VPAD
#define PAD_N   95.0f         // 100096 - 100001 zero rows, each contributes 2^0 = 1
#define GX      74
#define ESTRIDE 80            // smem row stride for 64B fp8 rows (conflict-free)
#define CVT_N   (NV_V * ND / 16)         // 400004 16-byte packs
#define CVT_B   ((CVT_N + 511) / 512)    // 782 blocks @ 512 threads

// ---------------- device-global scratch ----------------
__device__ __align__(256) uint8_t g_E8[(size_t)NV_VPAD * ND];   // e4m3 item_emb; tail rows zero
__device__ __align__(256) uint8_t g_Q8[NB * ND];                // e4m3 Q, pre-scaled by log2(e)
__device__ float g_Spart[NB][GX];                // partial denominators, row-contiguous
__device__ float g_LP[NB];                       // exact logit at pred[b]

__device__ __forceinline__ uint32_t smem_u32(const void* p) {
    uint32_t a;
    asm("{ .reg .u64 t; cvta.to.shared.u64 t, %1; cvt.u32.u64 %0, t; }" : "=r"(a) : "l"(p));
    return a;
}
__device__ __forceinline__ float ex2f(float x) {
    float r; asm("ex2.approx.ftz.f32 %0, %1;" : "=f"(r) : "f"(x)); return r;
}
__device__ __forceinline__ void cp_async16(uint32_t dst, const void* src) {
    asm volatile("cp.async.cg.shared.global [%0], [%1], 16;" :: "r"(dst), "l"(src) : "memory");
}
// pack (lo, hi) floats into e4m3x2 (low byte = lo)
__device__ __forceinline__ uint16_t cvt2_e4m3(float lo, float hi) {
    uint16_t r;
    asm("cvt.rn.satfinite.e4m3x2.f32 %0, %1, %2;" : "=h"(r) : "f"(hi), "f"(lo));
    return r;
}
__device__ __forceinline__ uint32_t cvt4_e4m3(float a, float b, float c, float d) {
    return (uint32_t)cvt2_e4m3(a, b) | ((uint32_t)cvt2_e4m3(c, d) << 16);
}

// ---------------- K1: fused [q-pooling | fp32 -> e4m3 convert], 512 threads ----------------
__global__ __launch_bounds__(512) void prep_kernel(const int* __restrict__ log_seqs,
                                                   const int* __restrict__ pred,
                                                   const float* __restrict__ item_emb,
                                                   const float* __restrict__ attn_key,
                                                   const float* __restrict__ pos_emb) {
    __shared__ __nv_bfloat16 sseq[NL][ND + 2];   // 26.4 KB; 132B row stride
    __shared__ int   sids[NL];
    __shared__ float ssim[NL];
    __shared__ float skey[ND];
    __shared__ float sred[16];
    __shared__ float sq[8][ND];
    __shared__ float sqf[ND];

    const int t = threadIdx.x;

    if (blockIdx.x >= NB) {
        // ---- convert branch: 16 floats -> 16 e4m3 bytes per thread ----
        int i = (blockIdx.x - NB) * 512 + t;
        if (i < CVT_N) {
            const float4* src = reinterpret_cast<const float4*>(item_emb) + 4 * (size_t)i;
            float4 v0 = src[0], v1 = src[1], v2 = src[2], v3 = src[3];
            uint4 p;
            p.x = cvt4_e4m3(v0.x, v0.y, v0.z, v0.w);
            p.y = cvt4_e4m3(v1.x, v1.y, v1.z, v1.w);
            p.z = cvt4_e4m3(v2.x, v2.y, v2.z, v2.w);
            p.w = cvt4_e4m3(v3.x, v3.y, v3.z, v3.w);
            reinterpret_cast<uint4*>(g_E8)[i] = p;
        }
        return;
    }

    // ---- q-pooling branch (16 warps) ----
    const int b = blockIdx.x;
    const int w = t >> 5, lane = t & 31;
    if (t < ND) skey[t] = attn_key[t];
    if (t < NL) sids[t] = log_seqs[b * NL + t];
    __syncthreads();

    // gather: warp w covers rows w, w+16, ..., 13 iterations
    int myid = 0;
    if (lane < 13 && w + lane * 16 < NL) myid = sids[w + lane * 16];
    #pragma unroll
    for (int i = 0; i < 13; i++) {
        int l = w + i * 16;
        if (l < NL) {
            int id = __shfl_sync(0xFFFFFFFFu, myid, i);
            int d0 = lane * 2;
            float2 e = *reinterpret_cast<const float2*>(item_emb + (size_t)id * ND + d0);
            float2 p = *reinterpret_cast<const float2*>(pos_emb + l * ND + d0);
            float v0 = 0.f, v1 = 0.f;
            if (id != 0) { v0 = fmaf(e.x, 8.f, p.x); v1 = fmaf(e.y, 8.f, p.y); }
            *reinterpret_cast<__nv_bfloat162*>(&sseq[l][d0]) = __floats2bfloat162_rn(v0, v1);
        }
    }
    __syncthreads();

    // sim: thread-per-row dot product from smem (33-word row stride, conflict-free)
    if (t < NL) {
        const __nv_bfloat162* row = reinterpret_cast<const __nv_bfloat162*>(sseq[t]);
        float sim = 0.f;
        #pragma unroll
        for (int d2 = 0; d2 < 32; d2++) {
            __nv_bfloat162 sv = row[d2];
            sim = fmaf(__bfloat162float(__low2bfloat16(sv)),  skey[2 * d2],     sim);
            sim = fmaf(__bfloat162float(__high2bfloat16(sv)), skey[2 * d2 + 1], sim);
        }
        ssim[t] = (sids[t] != 0) ? sim : -1e30f;
    }
    __syncthreads();

    // softmax over L (16-warp block reduce)
    float v = (t < NL) ? ssim[t] : -1e30f;
    float m = v;
    #pragma unroll
    for (int o = 16; o > 0; o >>= 1) m = fmaxf(m, __shfl_xor_sync(0xFFFFFFFFu, m, o));
    if (lane == 0) sred[w] = m;
    __syncthreads();
    if (t == 0) { float mm = sred[0]; for (int i = 1; i < 16; i++) mm = fmaxf(mm, sred[i]); sred[0] = mm; }
    __syncthreads();
    const float mx = sred[0];
    __syncthreads();
    float e = (t < NL) ? __expf(v - mx) : 0.f;
    if (t < NL) ssim[t] = e;
    float s = e;
    #pragma unroll
    for (int o = 16; o > 0; o >>= 1) s += __shfl_xor_sync(0xFFFFFFFFu, s, o);
    if (lane == 0) sred[w] = s;
    __syncthreads();
    if (t == 0) { float ss = 0.f; for (int i = 0; i < 16; i++) ss += sred[i]; sred[0] = ss; }
    __syncthreads();
    const float inv = 1.0f / sred[0];

    // pass 2: Q[d] = sum_l attn_l * seqs[l][d]  (8 groups of 64 threads)
    const int d = t & 63, gq = t >> 6;
    float acc = 0.f;
    for (int l = gq; l < NL; l += 8)
        acc += ssim[l] * __bfloat162float(sseq[l][d]);
    sq[gq][d] = acc;
    __syncthreads();
    if (t < ND) {
        float q = 0.f;
        #pragma unroll
        for (int i = 0; i < 8; i++) q += sq[i][t];
        q *= inv;
        sqf[t] = q * 1.44269504088896340736f;   // *log2(e), for fp8 Q
        int pid = pred[b];
        sq[0][t] = q * item_emb[(size_t)pid * ND + t];
    }
    __syncthreads();
    if (t < 32)   // pack Q to e4m3
        reinterpret_cast<uint16_t*>(g_Q8 + b * ND)[t] = cvt2_e4m3(sqf[2 * t], sqf[2 * t + 1]);
    if (t == 0) {
        float lp = 0.f;
        for (int i = 0; i < ND; i++) lp += sq[0][i];
        g_LP[b] = lp;
    }
}

// ---------------- K2: fused FP8 GEMM (mma.sync e4m3, f16 accum) + exp2-sum ----------------
// Grid (GX, 8). 128-row chunks, 3-stage cp.async ring; warp w owns 16 M rows.
__global__ __launch_bounds__(256) void gemm_kernel() {
    __shared__ __align__(16) char sE[3][128 * ESTRIDE];   // 30 KB ring
    const int t = threadIdx.x, w = t >> 5, lane = t & 31;
    const int g = lane >> 2, tg = lane & 3;
    const int m0 = blockIdx.y * 128 + w * 16;
    uint32_t sb[3] = { smem_u32(sE[0]), smem_u32(sE[1]), smem_u32(sE[2]) };

    // A fragments: Q8[m0..m0+16) x k[0..64), 2 k-groups of 32
    uint32_t a[2][4];
    #pragma unroll
    for (int kk = 0; kk < 2; kk++) {
        const uint8_t* q0 = g_Q8 + (m0 + g) * ND + kk * 32 + tg * 4;
        const uint8_t* q1 = g_Q8 + (m0 + g + 8) * ND + kk * 32 + tg * 4;
        a[kk][0] = *reinterpret_cast<const uint32_t*>(q0);
        a[kk][1] = *reinterpret_cast<const uint32_t*>(q1);
        a[kk][2] = *reinterpret_cast<const uint32_t*>(q0 + 16);
        a[kk][3] = *reinterpret_cast<const uint32_t*>(q1 + 16);
    }

    float sum0 = 0.f, sum1 = 0.f;
    const uint32_t soff = (t >> 2) * ESTRIDE + (t & 3) * 16;   // rows t/4 and t/4+64
    const uint32_t goff = t * 16;

    // prefetch stages 0 and 1 (8 KB each)
    #pragma unroll
    for (int p = 0; p < 2; p++) {
        int cc = blockIdx.x + p * GX;
        if (cc < NCH) {
            const uint8_t* src = g_E8 + (size_t)cc * 8192;
            cp_async16(sb[p] + soff, src + goff);
            cp_async16(sb[p] + soff + 64 * ESTRIDE, src + goff + 4096);
        }
        asm volatile("cp.async.commit_group;" ::: "memory");
    }

    int ph = 0;
    for (int c = blockIdx.x; c < NCH; c += GX) {
        asm volatile("cp.async.wait_group 1;" ::: "memory");
        __syncthreads();

        int cn = c + 2 * GX;
        int pn = ph + 2; if (pn >= 3) pn -= 3;
        if (cn < NCH) {
            const uint8_t* src = g_E8 + (size_t)cn * 8192;
            cp_async16(sb[pn] + soff, src + goff);
            cp_async16(sb[pn] + soff + 64 * ESTRIDE, src + goff + 4096);
        }
        asm volatile("cp.async.commit_group;" ::: "memory");

        const char* buf = sE[ph];
        #pragma unroll
        for (int nt = 0; nt < 16; nt++) {
            uint32_t c01 = 0u, c23 = 0u;   // f16x2 accumulators
            const char* bp = buf + (nt * 8 + g) * ESTRIDE + tg * 4;
            #pragma unroll
            for (int kk = 0; kk < 2; kk++) {
                uint32_t b0 = *reinterpret_cast<const uint32_t*>(bp + kk * 32);
                uint32_t b1 = *reinterpret_cast<const uint32_t*>(bp + kk * 32 + 16);
                asm volatile(
                    "mma.sync.aligned.m16n8k32.row.col.f16.e4m3.e4m3.f16 "
                    "{%0,%1}, {%2,%3,%4,%5}, {%6,%7}, {%0,%1};"
                    : "+r"(c01), "+r"(c23)
                    : "r"(a[kk][0]), "r"(a[kk][1]), "r"(a[kk][2]), "r"(a[kk][3]),
                      "r"(b0), "r"(b1));
            }
            float2 f01 = __half22float2(*reinterpret_cast<const __half2*>(&c01));
            float2 f23 = __half22float2(*reinterpret_cast<const __half2*>(&c23));
            sum0 += ex2f(f01.x) + ex2f(f01.y);   // rows m0+g
            sum1 += ex2f(f23.x) + ex2f(f23.y);   // rows m0+g+8
        }
        ph = ph + 1 == 3 ? 0 : ph + 1;
    }

    sum0 += __shfl_xor_sync(0xFFFFFFFFu, sum0, 1);
    sum0 += __shfl_xor_sync(0xFFFFFFFFu, sum0, 2);
    sum1 += __shfl_xor_sync(0xFFFFFFFFu, sum1, 1);
    sum1 += __shfl_xor_sync(0xFFFFFFFFu, sum1, 2);
    if (tg == 0) {
        g_Spart[m0 + g][blockIdx.x] = sum0;
        g_Spart[m0 + g + 8][blockIdx.x] = sum1;
    }
}

// ---------------- K3: reduce partials + final gather (warp per row) ----------------
__global__ __launch_bounds__(256) void final_kernel(float* __restrict__ out) {
    const int gw = (blockIdx.x * 256 + threadIdx.x) >> 5;
    const int lane = threadIdx.x & 31;
    if (gw < NB) {
        float s = 0.f;
        for (int x = lane; x < GX; x += 32) s += g_Spart[gw][x];
        #pragma unroll
        for (int o = 16; o > 0; o >>= 1) s += __shfl_xor_sync(0xFFFFFFFFu, s, o);
        if (lane == 0) out[gw] = __expf(g_LP[gw]) / (s - PAD_N);
    }
}

// ---------------- launch ----------------
extern "C" void kernel_launch(void* const* d_in, const int* in_sizes, int n_in,
                              void* d_out, int out_size) {
    const int*   log_seqs = (const int*)d_in[0];
    const int*   pred     = (const int*)d_in[1];
    const float* item_emb = (const float*)d_in[2];
    const float* attn_key = (const float*)d_in[3];
    const float* pos_emb  = (const float*)d_in[4];
    float* out = (float*)d_out;

    prep_kernel<<<NB + CVT_B, 512>>>(log_seqs, pred, item_emb, attn_key, pos_emb);
    gemm_kernel<<<dim3(GX, NB / 128, 1), 256>>>();
    final_kernel<<<NB * 32 / 256, 256>>>(out);
}